// round 11
// baseline (speedup 1.0000x reference)
#include <cuda_runtime.h>

#define H   128
#define FF  8
#define C4  512
#define MB  14
#define NT  256
#define BB  2048
#define KH  64
#define HS  20     // hsm row stride (floats): 16B-aligned, 4-way store conflict
#define L2E 1.4426950408889634f

// U blocked as UG[k][j][gate] (float4 per (k,j)): coalesced LDG.128.
__device__ __align__(16) float g_UGe[H * C4];
__device__ __align__(16) float g_UGd[H * C4];

typedef unsigned long long u64;

__device__ __forceinline__ u64 dup2(float v) {
    u64 r; asm("mov.b64 %0, {%1, %1};" : "=l"(r) : "f"(v)); return r;
}
__device__ __forceinline__ u64 pack2(float lo, float hi) {
    u64 r; asm("mov.b64 %0, {%1, %2};" : "=l"(r) : "f"(lo), "f"(hi)); return r;
}
__device__ __forceinline__ void fma2(u64& d, u64 a, u64 b) {
    asm("fma.rn.f32x2 %0, %1, %2, %0;" : "+l"(d) : "l"(a), "l"(b));
}
__device__ __forceinline__ void add2(u64& d, u64 a) {
    asm("add.rn.f32x2 %0, %0, %1;" : "+l"(d) : "l"(a));
}
__device__ __forceinline__ void unpack2(u64 v, float& lo, float& hi) {
    asm("mov.b64 {%0, %1}, %2;" : "=f"(lo), "=f"(hi) : "l"(v));
}
__device__ __forceinline__ float ex2f(float x){ float r; asm("ex2.approx.f32 %0, %1;" : "=f"(r) : "f"(x)); return r; }
__device__ __forceinline__ float rcpf(float x){ float r; asm("rcp.approx.f32 %0, %1;" : "=f"(r) : "f"(x)); return r; }

#define BARSYNC() asm volatile("bar.sync 0;" ::: "memory")

// i/f/o sigmoids + g tanh for one row, one shared rcp per (i,f) and (g,o).
// Safe: |z| < ~20 here, so the products cannot overflow.
__device__ __forceinline__ void gates_row(float zi, float zf, float zg, float zo,
                                          float cin, float& cout, float& so) {
    float di = 1.f + ex2f(-L2E * zi);
    float df = 1.f + ex2f(-L2E * zf);
    float r  = rcpf(di * df);
    float si = r * df, sf = r * di;
    float dg = 1.f + ex2f(2.f * L2E * zg);
    float dd = 1.f + ex2f(-L2E * zo);
    float r2 = rcpf(dg * dd);
    float tg = fmaf(-2.f, r2 * dd, 1.f);
    so = r2 * dg;
    cout = fmaf(sf, cin, si * tg);
}

// 7 row-pairs from a stride-HS row (base 16B-aligned): 3x LDS.128 + 1x LDS.64
__device__ __forceinline__ void load_pairs7(u64* hp, const float* row) {
    ulonglong2 a = *(const ulonglong2*)(row);
    ulonglong2 b = *(const ulonglong2*)(row + 4);
    ulonglong2 c = *(const ulonglong2*)(row + 8);
    hp[0] = a.x; hp[1] = a.y; hp[2] = b.x; hp[3] = b.y;
    hp[4] = c.x; hp[5] = c.y;
    hp[6] = *(const u64*)(row + 12);
}

__global__ void transposeU_kernel(const float* __restrict__ Ue, const float* __restrict__ Ud) {
    int i = blockIdx.x * blockDim.x + threadIdx.x;
    if (i < H * C4) {
        int k = i / C4, c = i % C4;
        int o = (k * H + (c & 127)) * 4 + (c >> 7);
        g_UGe[o] = Ue[i];
        g_UGd[o] = Ud[i];
    }
}

// dyn smem (floats): hsm[2][128][HS] | xring[3][8][16] | ysm[8][16] | wsm | wosm | zex2
#define SM_H   0
#define SM_XR  5120
#define SM_Y   5504
#define SM_W   5632
#define SM_WO  9728
#define SM_ZX  10752
#define SM_FLOATS 17920

// Group G: k in [G*64, G*64+64). G0 keeps pairs 0-3 (rows 0-7) and the x
// prefetch/decoder head threads; G1 keeps pairs 4-6. Bias + x@W are folded
// into the keeper; only h@U partials of non-kept pairs cross via zex2.
template<int G>
__device__ __forceinline__ void lstm_body(
    int tid, int rs, int T,
    const float* __restrict__ x,
    const float* __restrict__ We, const float* __restrict__ be,
    const float* __restrict__ Wd, const float* __restrict__ bd,
    const float* __restrict__ bog,
    float* __restrict__ out,
    float* hsm, float* xring, float* ysm, float* wsm, const float* wosm,
    ulonglong2* zex2)
{
    constexpr int KK0 = G * KH;
    constexpr int P0  = G ? 4 : 0;            // kept pairs [P0, P0+NPk)
    constexpr int NPk = G ? 3 : 4;
    constexpr int W0  = G ? 0 : 4;            // crossing pairs [W0, W0+NPw)
    constexpr int NPw = G ? 4 : 3;

    const int j = tid & (H - 1);
    const int  xm = tid >> 3, xf = tid & 7;
    const bool xth = tid < MB * FF;           // G0-only helper threads
    const bool gx  = xth && (rs + xm < BB);
    const float bof = bog[xf];
    const float* xrow = x   + (size_t)(rs + xm) * T * FF + xf;
    float*       orow = out + (size_t)(rs + xm) * T * FF + xf;

    float cst[2 * NPk];
    #pragma unroll
    for (int i = 0; i < 2 * NPk; i++) cst[i] = 0.f;

    int buf = 0;

    for (int phase = 0; phase < 2; phase++) {
        const bool dec = (phase == 1);
        const float4* UG4j = ((const float4*)(dec ? g_UGd : g_UGe)) + j;
        const float*  Wm   = dec ? Wd : We;
        const float*  bv   = dec ? bd : be;

        for (int i = tid; i < FF * C4; i += NT) {      // stage W [f][j][g]
            int f = i >> 9, c = i & 511;
            wsm[(f * H + (c & 127)) * 4 + (c >> 7)] = Wm[i];
        }
        u64 bdv[4];
        #pragma unroll
        for (int g = 0; g < 4; g++) bdv[g] = dup2(bv[g * H + j]);
        if (dec && gx) ysm[xf * 16 + xm] = xrow[(size_t)(T - 1) * FF];  // y0 = x[:,T-1,:]
        BARSYNC();

        for (int t = 0; t < T; t++) {
            const int nbuf = buf ^ 1;
            const float* hbuf = hsm + buf  * (H * HS);
            float*       hnew = hsm + nbuf * (H * HS);

            if (dec) BARSYNC();               // BAR_A (decoder: before reading ysm)

            // ---- acc init + x@W for kept pairs ----
            u64 acc[4][7];
            #pragma unroll
            for (int g = 0; g < 4; g++)
                #pragma unroll
                for (int p = 0; p < 7; p++)
                    acc[g][p] = (p >= P0 && p < P0 + NPk) ? bdv[g] : 0ull;

            {
                const float* xb = dec ? ysm : (xring + (t % 3) * 128);
                #pragma unroll
                for (int f = 0; f < FF; f++) {
                    float4 wf4 = ((const float4*)wsm)[f * H + j];
                    u64 xp[NPk];
                    #pragma unroll
                    for (int pi = 0; pi < NPk; pi++)
                        xp[pi] = *(const u64*)(xb + f * 16 + 2 * (P0 + pi));
                    #pragma unroll
                    for (int g = 0; g < 4; g++) {
                        u64 wd = dup2(((const float*)&wf4)[g]);
                        #pragma unroll
                        for (int pi = 0; pi < NPk; pi++) fma2(acc[g][P0 + pi], xp[pi], wd);
                    }
                }
            }

            if (!dec) BARSYNC();              // BAR_A (encoder: h(t-1)/zex drained)

            // ---- h @ U over k in [KK0, KK0+64): 16 blocks of 4k, ring depth 2 ----
            float4 ur0[4], ur1[4];
            {
                const float4* u0p = UG4j + KK0 * H;
                #pragma unroll
                for (int q = 0; q < 4; q++) { ur0[q] = u0p[q * H]; ur1[q] = u0p[(4 + q) * H]; }
            }
            const float4* uld = UG4j + (KK0 + 8) * H;  // next block to load
            const float*  hq  = hbuf + KK0 * HS;

            #pragma unroll 1
            for (int kb2 = 0; kb2 < 7; kb2++) {
                // consume ur0 (block 2*kb2), reload it with block 2*kb2+2
                #pragma unroll
                for (int q = 0; q < 4; q++) {
                    u64 hp[7];
                    load_pairs7(hp, hq + q * HS);
                    #pragma unroll
                    for (int g = 0; g < 4; g++) {
                        u64 d = dup2(((const float*)&ur0[q])[g]);
                        #pragma unroll
                        for (int p = 0; p < 7; p++) fma2(acc[g][p], hp[p], d);
                    }
                }
                #pragma unroll
                for (int q = 0; q < 4; q++) ur0[q] = uld[q * H];
                hq += 4 * HS;
                // consume ur1 (block 2*kb2+1), reload it with block 2*kb2+3
                #pragma unroll
                for (int q = 0; q < 4; q++) {
                    u64 hp[7];
                    load_pairs7(hp, hq + q * HS);
                    #pragma unroll
                    for (int g = 0; g < 4; g++) {
                        u64 d = dup2(((const float*)&ur1[q])[g]);
                        #pragma unroll
                        for (int p = 0; p < 7; p++) fma2(acc[g][p], hp[p], d);
                    }
                }
                #pragma unroll
                for (int q = 0; q < 4; q++) ur1[q] = uld[(4 + q) * H];
                hq  += 4 * HS;
                uld += 8 * H;
            }
            #pragma unroll
            for (int kb = 0; kb < 2; kb++) {   // tail blocks 14 (ur0), 15 (ur1)
                #pragma unroll
                for (int q = 0; q < 4; q++) {
                    u64 hp[7];
                    load_pairs7(hp, hq + q * HS);
                    const float4& uu = kb ? ur1[q] : ur0[q];
                    #pragma unroll
                    for (int g = 0; g < 4; g++) {
                        u64 d = dup2(((const float*)&uu)[g]);
                        #pragma unroll
                        for (int p = 0; p < 7; p++) fma2(acc[g][p], hp[p], d);
                    }
                }
                hq += 4 * HS;
            }

            // ---- cross non-kept h@U partials (2 gates per STS.128) ----
            #pragma unroll
            for (int pi = 0; pi < NPw; pi++) {
                const int p = W0 + pi;
                #pragma unroll
                for (int g2 = 0; g2 < 2; g2++) {
                    ulonglong2 v;
                    v.x = acc[2 * g2][p];
                    v.y = acc[2 * g2 + 1][p];
                    zex2[(g2 * 7 + p) * H + j] = v;
                }
            }
            BARSYNC();                         // BAR_B: zex ready

            // ---- gather + gates for kept pairs -> write h into other buffer ----
            u64* hrow = (u64*)(hnew + j * HS);
            #pragma unroll
            for (int pi = 0; pi < NPk; pi++) {
                const int p = P0 + pi;
                ulonglong2 e0 = zex2[(0 * 7 + p) * H + j];
                ulonglong2 e1 = zex2[(1 * 7 + p) * H + j];
                add2(acc[0][p], e0.x); add2(acc[1][p], e0.y);
                add2(acc[2][p], e1.x); add2(acc[3][p], e1.y);
                float zi0, zi1, zf0, zf1, zg0, zg1, zo0, zo1;
                unpack2(acc[0][p], zi0, zi1);
                unpack2(acc[1][p], zf0, zf1);
                unpack2(acc[2][p], zg0, zg1);
                unpack2(acc[3][p], zo0, zo1);
                float c0, c1, so0, so1;
                gates_row(zi0, zf0, zg0, zo0, cst[2 * pi    ], c0, so0);
                gates_row(zi1, zf1, zg1, zo1, cst[2 * pi + 1], c1, so1);
                cst[2 * pi    ] = c0;
                cst[2 * pi + 1] = c1;
                float dc0 = 1.f + ex2f(2.f * L2E * c0);
                float dc1 = 1.f + ex2f(2.f * L2E * c1);
                float rc  = rcpf(dc0 * dc1);
                float h0  = so0 * fmaf(-2.f, rc * dc1, 1.f);
                float h1  = so1 * fmaf(-2.f, rc * dc0, 1.f);
                hrow[p] = pack2(h0, h1);
            }

            if (!dec) {
                // prefetch x(t+2) into ring slot (t+2)%3 (read two steps later)
                if (G == 0 && gx && t + 2 < T)
                    (xring + ((t + 2) % 3) * 128)[xf * 16 + xm] = xrow[(size_t)(t + 2) * FF];
            } else {
                BARSYNC();                     // BAR_C: h(t) complete
                if (xth) {
                    float a = 0.f, b2 = 0.f, c2 = 0.f, d2 = 0.f;
                    #pragma unroll 8
                    for (int k = 0; k < H; k += 4) {
                        a  = fmaf(hnew[(k    ) * HS + xm], wosm[(k    ) * FF + xf], a);
                        b2 = fmaf(hnew[(k + 1) * HS + xm], wosm[(k + 1) * FF + xf], b2);
                        c2 = fmaf(hnew[(k + 2) * HS + xm], wosm[(k + 2) * FF + xf], c2);
                        d2 = fmaf(hnew[(k + 3) * HS + xm], wosm[(k + 3) * FF + xf], d2);
                    }
                    float y = fmaxf(bof + ((a + b2) + (c2 + d2)), 0.f);
                    ysm[xf * 16 + xm] = y;
                    if (gx) orow[(size_t)t * FF] = y;
                }
            }
            buf = nbuf;
        }
    }
}

__global__ void __launch_bounds__(NT, 1)
lstm_ae_kernel(const float* __restrict__ x,
               const float* __restrict__ We, const float* __restrict__ be,
               const float* __restrict__ Wd, const float* __restrict__ bd,
               const float* __restrict__ Wo, const float* __restrict__ bog,
               float* __restrict__ out, int T)
{
    extern __shared__ __align__(16) float sm[];
    float*       hsm   = sm + SM_H;
    float*       xring = sm + SM_XR;
    float*       ysm   = sm + SM_Y;
    float*       wsm   = sm + SM_W;
    float*       wosm  = sm + SM_WO;
    ulonglong2*  zex2  = (ulonglong2*)(sm + SM_ZX);

    const int tid = threadIdx.x;
    const int rs  = blockIdx.x * MB;

    for (int i = tid; i < SM_W; i += NT) sm[i] = 0.f;       // hsm + xring + ysm
    for (int i = tid; i < H * FF; i += NT) wosm[i] = Wo[i];
    {   // prefill ring slots for t = 0, 1
        const int xm = tid >> 3, xf = tid & 7;
        if (tid < MB * FF && rs + xm < BB) {
            const float* xr = x + (size_t)(rs + xm) * T * FF + xf;
            xring[0 * 128 + xf * 16 + xm] = xr[0];
            xring[1 * 128 + xf * 16 + xm] = xr[FF];
        }
    }
    __syncthreads();

    if (tid < 128)
        lstm_body<0>(tid, rs, T, x, We, be, Wd, bd, bog, out, hsm, xring, ysm, wsm, wosm, zex2);
    else
        lstm_body<1>(tid, rs, T, x, We, be, Wd, bd, bog, out, hsm, xring, ysm, wsm, wosm, zex2);
}

extern "C" void kernel_launch(void* const* d_in, const int* in_sizes, int n_in,
                              void* d_out, int out_size)
{
    const float* x  = (const float*)d_in[0];
    const float* We = (const float*)d_in[1];
    const float* Ue = (const float*)d_in[2];
    const float* be = (const float*)d_in[3];
    const float* Wd = (const float*)d_in[4];
    const float* Ud = (const float*)d_in[5];
    const float* bd = (const float*)d_in[6];
    const float* Wo = (const float*)d_in[7];
    const float* bo = (const float*)d_in[8];
    float* out = (float*)d_out;

    const int T = in_sizes[0] / (BB * FF);
    const int SMEM_BYTES = SM_FLOATS * 4;

    cudaFuncSetAttribute(lstm_ae_kernel,
                         cudaFuncAttributeMaxDynamicSharedMemorySize, SMEM_BYTES);

    transposeU_kernel<<<(H * C4 + 255) / 256, 256>>>(Ue, Ud);
    lstm_ae_kernel<<<(BB + MB - 1) / MB, NT, SMEM_BYTES>>>(x, We, be, Wd, bd, Wo, bo, out, T);
}

// round 13
// speedup vs baseline: 1.5326x; 1.5326x over previous
#include <cuda_runtime.h>
#include <cuda_bf16.h>

#define H    128
#define FF   8
#define MB   14
#define NT   256
#define BB   2048
#define L2E  1.4426950408889634f

typedef unsigned long long u64;
typedef unsigned int u32;
typedef unsigned short u16;

// A fragments, mma.sync m16n8k16 layout: [phase][(w*8+kc)*4+mt][lane] uint4
__device__ __align__(16) uint4 g_AFhi[2 * 8192];
__device__ __align__(16) uint4 g_AFlo[2 * 8192];

// ---- dyn smem byte offsets ----
#define SAF 0          // A_hi fragments (131072)
#define SBF 131072     // B fragments: [buf][hl][kc][lane] uint4 (16384)
#define SZ  147456     // zsm [512][20] f32 (40960)
#define SW  188416     // W blocked [f][m][g] f32 (16384)
#define SWO 204800     // W_out (4096)
#define SHS 208896     // h fp32 [j][18] decoder staging (9216)
#define SX  218112     // x double buffer 2 x (8f x 16n) f32 (1024)
#define SY  219136     // y staging 8f x 16n f32 (512)
#define SMEM_BYTES 219648

__device__ __forceinline__ float ex2f(float x){ float r; asm("ex2.approx.f32 %0, %1;" : "=f"(r) : "f"(x)); return r; }
__device__ __forceinline__ float rcpf(float x){ float r; asm("rcp.approx.f32 %0, %1;" : "=f"(r) : "f"(x)); return r; }
__device__ __forceinline__ u16 bf16bits(float v) {
    __nv_bfloat16 h = __float2bfloat16(v); return *(u16*)&h;
}
__device__ __forceinline__ float bf16val(u16 b) {
    __nv_bfloat16 h = *(__nv_bfloat16*)&b; return __bfloat162float(h);
}

// D += A(16x16 bf16) x B(16x8 bf16), fp32 accum — base ISA, sm_80+
__device__ __forceinline__ void mma16816(float* d, uint4 a, u32 b0, u32 b1) {
    asm volatile("mma.sync.aligned.m16n8k16.row.col.f32.bf16.bf16.f32 "
        "{%0,%1,%2,%3}, {%4,%5,%6,%7}, {%8,%9}, {%0,%1,%2,%3};"
        : "+f"(d[0]), "+f"(d[1]), "+f"(d[2]), "+f"(d[3])
        : "r"(a.x), "r"(a.y), "r"(a.z), "r"(a.w), "r"(b0), "r"(b1));
}

// ---- prep: build A fragments (hi/lo bf16 split of U^T) ----
__global__ void prep_kernel(const float* __restrict__ Ue, const float* __restrict__ Ud) {
    int i = blockIdx.x * blockDim.x + threadIdx.x;
    if (i >= 16384) return;
    int p = i >> 13, idx = i & 8191;
    int lane = idx & 31, mt = (idx >> 5) & 3, kc = (idx >> 7) & 7, w = idx >> 10;
    const float* U = p ? Ud : Ue;
    int r0 = lane >> 2, kb = kc * 16 + (lane & 3) * 2;
    int c0 = w * 64 + mt * 16 + r0;      // A row = gate col of U
    int ks[4] = { kb, kb, kb + 8, kb + 8 };
    int cs[4] = { c0, c0 + 8, c0, c0 + 8 };
    u32 hi[4], lo[4];
    #pragma unroll
    for (int q = 0; q < 4; q++) {
        float v0 = U[ks[q] * 512 + cs[q]];
        float v1 = U[(ks[q] + 1) * 512 + cs[q]];
        u16 h0 = bf16bits(v0), h1 = bf16bits(v1);
        u16 l0 = bf16bits(v0 - bf16val(h0));
        u16 l1 = bf16bits(v1 - bf16val(h1));
        hi[q] = (u32)h0 | ((u32)h1 << 16);
        lo[q] = (u32)l0 | ((u32)l1 << 16);
    }
    g_AFhi[p * 8192 + idx] = make_uint4(hi[0], hi[1], hi[2], hi[3]);
    g_AFlo[p * 8192 + idx] = make_uint4(lo[0], lo[1], lo[2], lo[3]);
}

__global__ void __launch_bounds__(NT, 1)
lstm_mma_kernel(const float* __restrict__ x,
                const float* __restrict__ We, const float* __restrict__ be,
                const float* __restrict__ Wd, const float* __restrict__ bd,
                const float* __restrict__ Wo, const float* __restrict__ bog,
                float* __restrict__ out, int T)
{
    extern __shared__ __align__(16) char sm[];
    uint4* afh = (uint4*)(sm + SAF);
    uint4* bfr = (uint4*)(sm + SBF);
    u16*   bfu = (u16*)(sm + SBF);
    float* zsm = (float*)(sm + SZ);
    float* wsm = (float*)(sm + SW);
    float* wosm = (float*)(sm + SWO);
    float* hsm = (float*)(sm + SHS);
    float* xsm = (float*)(sm + SX);
    float* ysm = (float*)(sm + SY);

    const int tid  = threadIdx.x;
    const int wp   = tid >> 5, lane = tid & 31;
    const int rs   = blockIdx.x * MB;
    const int m    = tid & 127;            // gate unit j
    const int n0   = (tid >> 7) * 8;       // batch-row half
    const int nlim = (tid < 128) ? 8 : (MB - 8);

    // B-fragment scatter constants for k = m
    const int kcB = m >> 4, kk = m & 15;
    const int tb  = (kk >> 1) & 3, regB = kk >> 3, bitB = kk & 1;

    const int  xm = tid >> 3, xf = tid & 7;
    const bool xth = tid < MB * FF;
    const bool gx  = xth && (rs + xm < BB);
    const float bof = bog[xf];
    const float* xrow = x   + (size_t)(rs + xm) * T * FF + xf;
    float*       orow = out + (size_t)(rs + xm) * T * FF + xf;

    for (int i = tid; i < 4096; i += NT) ((u32*)(sm + SBF))[i] = 0;   // BF (h0 = 0)
    for (int i = tid; i < 384; i += NT) xsm[i] = 0.f;                 // xsm + ysm
    for (int i = tid; i < H * FF; i += NT) wosm[i] = Wo[i];
    if (gx) xsm[xf * 16 + xm] = xrow[0];

    float cst[8];
    #pragma unroll
    for (int i = 0; i < 8; i++) cst[i] = 0.f;
    int buf = 0;

    for (int phase = 0; phase < 2; phase++) {
        const bool dec = (phase == 1);
        const uint4* gafh = g_AFhi + phase * 8192;
        const uint4* gafl = g_AFlo + phase * 8192;
        const float* Wm = dec ? Wd : We;
        const float* bv = dec ? bd : be;

        for (int i = tid; i < 8192; i += NT) afh[i] = gafh[i];        // A_hi -> smem
        for (int i = tid; i < 4096; i += NT) {                        // W [f][m][g]
            int f = i >> 9, c = i & 511;
            wsm[((f << 7) + (c & 127)) * 4 + (c >> 7)] = Wm[i];
        }
        float bg[4];
        #pragma unroll
        for (int g = 0; g < 4; g++) bg[g] = bv[g * H + m];
        if (dec && gx) ysm[xf * 16 + xm] = xrow[(size_t)(T - 1) * FF];  // y0 = x[:,T-1,:]
        __syncthreads();

        for (int t = 0; t < T; t++) {
            // ---- x@W + bias (exact fp32; overlaps with HMMAs below) ----
            const float* xb = dec ? ysm : (xsm + (t & 1) * 128);
            float xw[4][8];
            #pragma unroll
            for (int g = 0; g < 4; g++)
                #pragma unroll
                for (int c = 0; c < 8; c++) xw[g][c] = bg[g];
            #pragma unroll
            for (int f = 0; f < FF; f++) {
                float4 w4 = ((const float4*)wsm)[f * 128 + m];
                #pragma unroll
                for (int c = 0; c < 8; c++) {
                    float xv = xb[f * 16 + n0 + c];
                    xw[0][c] = fmaf(xv, w4.x, xw[0][c]);
                    xw[1][c] = fmaf(xv, w4.y, xw[1][c]);
                    xw[2][c] = fmaf(xv, w4.z, xw[2][c]);
                    xw[3][c] = fmaf(xv, w4.w, xw[3][c]);
                }
            }

            // ---- z = U^T h via mma.sync: 192 HMMA/warp ----
            float d[4][2][4];
            #pragma unroll
            for (int mt = 0; mt < 4; mt++)
                #pragma unroll
                for (int nt = 0; nt < 2; nt++)
                    #pragma unroll
                    for (int q = 0; q < 4; q++) d[mt][nt][q] = 0.f;

            uint4 alo[4], alon[4];
            #pragma unroll
            for (int mt = 0; mt < 4; mt++) alo[mt] = gafl[((wp * 8) * 4 + mt) * 32 + lane];

            #pragma unroll
            for (int kc = 0; kc < 8; kc++) {
                uint4 bh = bfr[((buf * 2 + 0) * 8 + kc) * 32 + lane];
                uint4 bl = bfr[((buf * 2 + 1) * 8 + kc) * 32 + lane];
                if (kc < 7) {
                    #pragma unroll
                    for (int mt = 0; mt < 4; mt++)
                        alon[mt] = gafl[((wp * 8 + kc + 1) * 4 + mt) * 32 + lane];
                }
                #pragma unroll
                for (int mt = 0; mt < 4; mt++) {
                    uint4 ah = afh[((wp * 8 + kc) * 4 + mt) * 32 + lane];
                    mma16816(d[mt][0], ah, bh.x, bh.y);     // Uhi * hhi
                    mma16816(d[mt][1], ah, bh.z, bh.w);
                    mma16816(d[mt][0], ah, bl.x, bl.y);     // Uhi * hlo
                    mma16816(d[mt][1], ah, bl.z, bl.w);
                    mma16816(d[mt][0], alo[mt], bh.x, bh.y); // Ulo * hhi
                    mma16816(d[mt][1], alo[mt], bh.z, bh.w);
                }
                #pragma unroll
                for (int mt = 0; mt < 4; mt++) alo[mt] = alon[mt];
            }

            // ---- D -> zsm (stride 20, conflict-free STS.64) ----
            #pragma unroll
            for (int mt = 0; mt < 4; mt++) {
                int row0 = wp * 64 + mt * 16 + (lane >> 2);
                #pragma unroll
                for (int nt = 0; nt < 2; nt++) {
                    int c = (lane & 3) * 2 + nt * 8;
                    *(float2*)&zsm[row0 * 20 + c]       = make_float2(d[mt][nt][0], d[mt][nt][1]);
                    *(float2*)&zsm[(row0 + 8) * 20 + c] = make_float2(d[mt][nt][2], d[mt][nt][3]);
                }
            }
            __syncthreads();   // BAR_A: zsm complete

            // ---- gates: all 4 gates of unit m, rows n0..n0+nlim-1 ----
            {
                float4 za[4], zb[4];
                #pragma unroll
                for (int g = 0; g < 4; g++) {
                    za[g] = *(const float4*)&zsm[(g * 128 + m) * 20 + n0];
                    zb[g] = *(const float4*)&zsm[(g * 128 + m) * 20 + n0 + 4];
                }
                #pragma unroll
                for (int c = 0; c < 8; c++) {
                    float zi = ((c < 4) ? ((const float*)&za[0])[c] : ((const float*)&zb[0])[c - 4]) + xw[0][c];
                    float zf = ((c < 4) ? ((const float*)&za[1])[c] : ((const float*)&zb[1])[c - 4]) + xw[1][c];
                    float zg = ((c < 4) ? ((const float*)&za[2])[c] : ((const float*)&zb[2])[c - 4]) + xw[2][c];
                    float zo = ((c < 4) ? ((const float*)&za[3])[c] : ((const float*)&zb[3])[c - 4]) + xw[3][c];
                    float di = 1.f + ex2f(-L2E * zi);
                    float df = 1.f + ex2f(-L2E * zf);
                    float r  = rcpf(di * df);
                    float si = r * df, sf = r * di;
                    float dg = 1.f + ex2f(2.f * L2E * zg);
                    float dd = 1.f + ex2f(-L2E * zo);
                    float r2 = rcpf(dg * dd);
                    float tg = fmaf(-2.f, r2 * dd, 1.f);
                    float so = r2 * dg;
                    float cn = fmaf(sf, cst[c], si * tg);
                    cst[c] = cn;
                    float dc = 1.f + ex2f(2.f * L2E * cn);
                    float hv = so * fmaf(-2.f, rcpf(dc), 1.f);
                    if (c < nlim) {
                        int n = n0 + c;
                        int laneB = (n & 7) * 4 + tb, nt = n >> 3;
                        u16 hb = bf16bits(hv);
                        u16 lb = bf16bits(hv - bf16val(hb));
                        int nbuf = buf ^ 1;
                        bfu[((((nbuf * 2 + 0) * 8 + kcB) * 32 + laneB) << 3) + ((nt * 2 + regB) << 1) + bitB] = hb;
                        bfu[((((nbuf * 2 + 1) * 8 + kcB) * 32 + laneB) << 3) + ((nt * 2 + regB) << 1) + bitB] = lb;
                        if (dec) hsm[m * 18 + n] = hv;
                    }
                }
            }

            if (!dec) {
                if (gx && t + 1 < T)    // prefetch next x into other slot
                    xsm[((t + 1) & 1) * 128 + xf * 16 + xm] = xrow[(size_t)(t + 1) * FF];
            } else {
                __syncthreads();        // BAR_C: hsm complete
                if (xth) {
                    float a = 0.f, b2 = 0.f;
                    #pragma unroll 8
                    for (int k = 0; k < H; k += 2) {
                        a  = fmaf(hsm[(k    ) * 18 + xm], wosm[(k    ) * FF + xf], a);
                        b2 = fmaf(hsm[(k + 1) * 18 + xm], wosm[(k + 1) * FF + xf], b2);
                    }
                    float y = fmaxf(bof + a + b2, 0.f);
                    ysm[xf * 16 + xm] = y;
                    if (gx) orow[(size_t)t * FF] = y;
                }
            }
            __syncthreads();            // BAR_B: BF(nbuf)/x/y ready for next step
            buf ^= 1;
        }
    }
}

extern "C" void kernel_launch(void* const* d_in, const int* in_sizes, int n_in,
                              void* d_out, int out_size)
{
    const float* x  = (const float*)d_in[0];
    const float* We = (const float*)d_in[1];
    const float* Ue = (const float*)d_in[2];
    const float* be = (const float*)d_in[3];
    const float* Wd = (const float*)d_in[4];
    const float* Ud = (const float*)d_in[5];
    const float* bd = (const float*)d_in[6];
    const float* Wo = (const float*)d_in[7];
    const float* bo = (const float*)d_in[8];
    float* out = (float*)d_out;

    const int T = in_sizes[0] / (BB * FF);

    prep_kernel<<<64, 256>>>(Ue, Ud);

    cudaFuncSetAttribute(lstm_mma_kernel,
                         cudaFuncAttributeMaxDynamicSharedMemorySize, SMEM_BYTES);
    lstm_mma_kernel<<<(BB + MB - 1) / MB, NT, SMEM_BYTES>>>(x, We, be, Wd, bd, Wo, bo, out, T);
}

// round 14
// speedup vs baseline: 1.7097x; 1.1156x over previous
#include <cuda_runtime.h>
#include <cuda_bf16.h>

#define H    128
#define FF   8
#define MB   14
#define NT   256
#define BB   2048
#define L2E  1.4426950408889634f

typedef unsigned long long u64;
typedef unsigned int u32;
typedef unsigned short u16;

// A fragments, m16n8k16 layout: [phase][(w*8+kc)*4+g][lane] uint4
// A row = g*128 + w*16 + r  (gate-aligned M tiling)
__device__ __align__(16) uint4 g_AFhi[2 * 8192];
__device__ __align__(16) uint4 g_AFlo[2 * 8192];

// ---- dyn smem byte offsets ----
#define SAF 0          // A_hi fragments (131072)
#define SBF 131072     // B fragments: [buf][hl][kc][lane] uint4 (16384)
#define SW  147456     // W blocked [f][m][g] f32 (16384)
#define SWO 163840     // W_out (4096)
#define SHS 167936     // h fp32 [j][18] decoder staging (9216)
#define SX  177152     // x double buffer 2 x (8f x 16n) f32 (1024)
#define SY  178176     // y staging 8f x 16n f32 (512)
#define SMEM_BYTES 178688

__device__ __forceinline__ float ex2f(float x){ float r; asm("ex2.approx.f32 %0, %1;" : "=f"(r) : "f"(x)); return r; }
__device__ __forceinline__ float rcpf(float x){ float r; asm("rcp.approx.f32 %0, %1;" : "=f"(r) : "f"(x)); return r; }
__device__ __forceinline__ u16 bf16bits(float v) {
    __nv_bfloat16 h = __float2bfloat16(v); return *(u16*)&h;
}
__device__ __forceinline__ float bf16val(u16 b) {
    __nv_bfloat16 h = *(__nv_bfloat16*)&b; return __bfloat162float(h);
}

// D += A(16x16 bf16) x B(16x8 bf16), fp32 accum — base ISA
__device__ __forceinline__ void mma16816(float* d, uint4 a, u32 b0, u32 b1) {
    asm volatile("mma.sync.aligned.m16n8k16.row.col.f32.bf16.bf16.f32 "
        "{%0,%1,%2,%3}, {%4,%5,%6,%7}, {%8,%9}, {%0,%1,%2,%3};"
        : "+f"(d[0]), "+f"(d[1]), "+f"(d[2]), "+f"(d[3])
        : "r"(a.x), "r"(a.y), "r"(a.z), "r"(a.w), "r"(b0), "r"(b1));
}

// ---- prep: A fragments (hi/lo bf16 split of U^T), gate-aligned tiling ----
__global__ void prep_kernel(const float* __restrict__ Ue, const float* __restrict__ Ud) {
    int i = blockIdx.x * blockDim.x + threadIdx.x;
    if (i >= 16384) return;
    int p = i >> 13, idx = i & 8191;
    int lane = idx & 31, g = (idx >> 5) & 3, kc = (idx >> 7) & 7, w = idx >> 10;
    const float* U = p ? Ud : Ue;
    int r0 = lane >> 2, kb = kc * 16 + (lane & 3) * 2;
    int c0 = g * 128 + w * 16 + r0;       // gate-aligned: tile g = gate g of units w*16..
    int ks[4] = { kb, kb, kb + 8, kb + 8 };
    int cs[4] = { c0, c0 + 8, c0, c0 + 8 };
    u32 hi[4], lo[4];
    #pragma unroll
    for (int q = 0; q < 4; q++) {
        float v0 = U[ks[q] * 512 + cs[q]];
        float v1 = U[(ks[q] + 1) * 512 + cs[q]];
        u16 h0 = bf16bits(v0), h1 = bf16bits(v1);
        u16 l0 = bf16bits(v0 - bf16val(h0));
        u16 l1 = bf16bits(v1 - bf16val(h1));
        hi[q] = (u32)h0 | ((u32)h1 << 16);
        lo[q] = (u32)l0 | ((u32)l1 << 16);
    }
    g_AFhi[p * 8192 + idx] = make_uint4(hi[0], hi[1], hi[2], hi[3]);
    g_AFlo[p * 8192 + idx] = make_uint4(lo[0], lo[1], lo[2], lo[3]);
}

__global__ void __launch_bounds__(NT, 1)
lstm_mma_kernel(const float* __restrict__ x,
                const float* __restrict__ We, const float* __restrict__ be,
                const float* __restrict__ Wd, const float* __restrict__ bd,
                const float* __restrict__ Wo, const float* __restrict__ bog,
                float* __restrict__ out, int T)
{
    extern __shared__ __align__(16) char sm[];
    uint4* afh = (uint4*)(sm + SAF);
    uint4* bfr = (uint4*)(sm + SBF);
    u16*   bfu = (u16*)(sm + SBF);
    float* wsm = (float*)(sm + SW);
    float* wosm = (float*)(sm + SWO);
    float* hsm = (float*)(sm + SHS);
    float* xsm = (float*)(sm + SX);
    float* ysm = (float*)(sm + SY);

    const int tid  = threadIdx.x;
    const int wp   = tid >> 5, lane = tid & 31;
    const int rs   = blockIdx.x * MB;
    const int j0   = wp * 16 + (lane >> 2);   // unit for d regs 0,1 (j1 = j0+8)
    const int cA   = (lane & 3) * 2;          // base batch-col

    // B-fragment scatter constants (k = unit j); kcB identical for j0, j1
    const int kcB = wp;

    const int  xm = tid >> 3, xf = tid & 7;
    const bool xth = tid < MB * FF;
    const bool gx  = xth && (rs + xm < BB);
    const float bof = bog[xf];
    const float* xrow = x   + (size_t)(rs + xm) * T * FF + xf;
    float*       orow = out + (size_t)(rs + xm) * T * FF + xf;

    for (int i = tid; i < 4096; i += NT) ((u32*)(sm + SBF))[i] = 0;   // B (h0 = 0)
    for (int i = tid; i < 384; i += NT) xsm[i] = 0.f;                 // xsm + ysm
    for (int i = tid; i < H * FF; i += NT) wosm[i] = Wo[i];
    if (gx) xsm[xf * 16 + xm] = xrow[0];

    float cst[2][4];
    #pragma unroll
    for (int u = 0; u < 2; u++)
        #pragma unroll
        for (int c = 0; c < 4; c++) cst[u][c] = 0.f;
    int buf = 0;

    for (int phase = 0; phase < 2; phase++) {
        const bool dec = (phase == 1);
        const uint4* gafh = g_AFhi + phase * 8192;
        const uint4* gafl = g_AFlo + phase * 8192;
        const float* Wm = dec ? Wd : We;
        const float* bv = dec ? bd : be;

        for (int i = tid; i < 8192; i += NT) afh[i] = gafh[i];        // A_hi -> smem
        for (int i = tid; i < 4096; i += NT) {                        // W [f][m][g]
            int f = i >> 9, c = i & 511;
            wsm[((f << 7) + (c & 127)) * 4 + (c >> 7)] = Wm[i];
        }
        float bgv[2][4];
        #pragma unroll
        for (int u = 0; u < 2; u++)
            #pragma unroll
            for (int g = 0; g < 4; g++) bgv[u][g] = bv[g * H + j0 + u * 8];
        if (dec && gx) ysm[xf * 16 + xm] = xrow[(size_t)(T - 1) * FF];  // y0
        __syncthreads();

        for (int t = 0; t < T; t++) {
            // ---- x@W + bias (exact fp32) for this thread's (unit, col) set ----
            const float* xb = dec ? ysm : (xsm + (t & 1) * 128);
            float xw[4][2][4];                     // [g][u][cc]; cc: nt*2+off
            #pragma unroll
            for (int g = 0; g < 4; g++)
                #pragma unroll
                for (int u = 0; u < 2; u++)
                    #pragma unroll
                    for (int c = 0; c < 4; c++) xw[g][u][c] = bgv[u][g];
            #pragma unroll
            for (int f = 0; f < FF; f++) {
                float4 w0 = ((const float4*)wsm)[f * 128 + j0];
                float4 w1 = ((const float4*)wsm)[f * 128 + j0 + 8];
                float xv[4] = { xb[f * 16 + cA],     xb[f * 16 + cA + 1],
                                xb[f * 16 + cA + 8], xb[f * 16 + cA + 9] };
                #pragma unroll
                for (int c = 0; c < 4; c++) {
                    xw[0][0][c] = fmaf(xv[c], w0.x, xw[0][0][c]);
                    xw[1][0][c] = fmaf(xv[c], w0.y, xw[1][0][c]);
                    xw[2][0][c] = fmaf(xv[c], w0.z, xw[2][0][c]);
                    xw[3][0][c] = fmaf(xv[c], w0.w, xw[3][0][c]);
                    xw[0][1][c] = fmaf(xv[c], w1.x, xw[0][1][c]);
                    xw[1][1][c] = fmaf(xv[c], w1.y, xw[1][1][c]);
                    xw[2][1][c] = fmaf(xv[c], w1.z, xw[2][1][c]);
                    xw[3][1][c] = fmaf(xv[c], w1.w, xw[3][1][c]);
                }
            }

            // ---- z = U^T h via mma.sync: 192 HMMA/warp, D stays in regs ----
            float d[4][2][4];                      // [g][nt][q]
            #pragma unroll
            for (int g = 0; g < 4; g++)
                #pragma unroll
                for (int nt = 0; nt < 2; nt++)
                    #pragma unroll
                    for (int q = 0; q < 4; q++) d[g][nt][q] = 0.f;

            uint4 alo[4], alon[4];
            #pragma unroll
            for (int g = 0; g < 4; g++) alo[g] = gafl[((wp * 8) * 4 + g) * 32 + lane];

            #pragma unroll
            for (int kc = 0; kc < 8; kc++) {
                uint4 bh = bfr[((buf * 2 + 0) * 8 + kc) * 32 + lane];
                uint4 bl = bfr[((buf * 2 + 1) * 8 + kc) * 32 + lane];
                if (kc < 7) {
                    #pragma unroll
                    for (int g = 0; g < 4; g++)
                        alon[g] = gafl[((wp * 8 + kc + 1) * 4 + g) * 32 + lane];
                }
                #pragma unroll
                for (int g = 0; g < 4; g++) {
                    uint4 ah = afh[((wp * 8 + kc) * 4 + g) * 32 + lane];
                    mma16816(d[g][0], ah, bh.x, bh.y);       // Uhi * hhi
                    mma16816(d[g][1], ah, bh.z, bh.w);
                    mma16816(d[g][0], ah, bl.x, bl.y);       // Uhi * hlo
                    mma16816(d[g][1], ah, bl.z, bl.w);
                    mma16816(d[g][0], alo[g], bh.x, bh.y);   // Ulo * hhi
                    mma16816(d[g][1], alo[g], bh.z, bh.w);
                }
                #pragma unroll
                for (int g = 0; g < 4; g++) alo[g] = alon[g];
            }

            // ---- gates straight from accumulators; scatter h into B(nbuf) ----
            const int nbuf = buf ^ 1;
            #pragma unroll
            for (int u = 0; u < 2; u++) {
                const int j  = j0 + u * 8;
                const int kk = j & 15;
                const int tb = (kk >> 1) & 3, regB = kk >> 3, bitB = kk & 1;
                #pragma unroll
                for (int cc = 0; cc < 4; cc++) {
                    const int nt = cc >> 1, off = cc & 1;
                    const int n  = cA + nt * 8 + off;
                    const int q  = u * 2 + off;
                    float zi = d[0][nt][q] + xw[0][u][cc];
                    float zf = d[1][nt][q] + xw[1][u][cc];
                    float zg = d[2][nt][q] + xw[2][u][cc];
                    float zo = d[3][nt][q] + xw[3][u][cc];
                    float di = 1.f + ex2f(-L2E * zi);
                    float df = 1.f + ex2f(-L2E * zf);
                    float r  = rcpf(di * df);
                    float si = r * df, sf = r * di;
                    float dg = 1.f + ex2f(2.f * L2E * zg);
                    float dd = 1.f + ex2f(-L2E * zo);
                    float r2 = rcpf(dg * dd);
                    float tg = fmaf(-2.f, r2 * dd, 1.f);
                    float so = r2 * dg;
                    float cn = fmaf(sf, cst[u][cc], si * tg);
                    cst[u][cc] = cn;
                    float dc = 1.f + ex2f(2.f * L2E * cn);
                    float hv = so * fmaf(-2.f, rcpf(dc), 1.f);
                    if (n < MB) {
                        const int laneB = (n & 7) * 4 + tb, ntB = n >> 3;
                        u16 hb = bf16bits(hv);
                        u16 lb = bf16bits(hv - bf16val(hb));
                        bfu[((((nbuf * 2 + 0) * 8 + kcB) * 32 + laneB) << 3) + ((ntB * 2 + regB) << 1) + bitB] = hb;
                        bfu[((((nbuf * 2 + 1) * 8 + kcB) * 32 + laneB) << 3) + ((ntB * 2 + regB) << 1) + bitB] = lb;
                        if (dec) hsm[j * 18 + n] = hv;
                    }
                }
            }

            if (!dec) {
                if (gx && t + 1 < T)    // prefetch next x into other slot
                    xsm[((t + 1) & 1) * 128 + xf * 16 + xm] = xrow[(size_t)(t + 1) * FF];
            } else {
                __syncthreads();        // hsm complete
                if (xth) {
                    float a = 0.f, b2 = 0.f;
                    #pragma unroll 8
                    for (int k = 0; k < H; k += 2) {
                        a  = fmaf(hsm[(k    ) * 18 + xm], wosm[(k    ) * FF + xf], a);
                        b2 = fmaf(hsm[(k + 1) * 18 + xm], wosm[(k + 1) * FF + xf], b2);
                    }
                    float y = fmaxf(bof + a + b2, 0.f);
                    ysm[xf * 16 + xm] = y;
                    if (gx) orow[(size_t)t * FF] = y;
                }
            }
            __syncthreads();            // B(nbuf) / x / y ready for next step
            buf ^= 1;
        }
    }
}

extern "C" void kernel_launch(void* const* d_in, const int* in_sizes, int n_in,
                              void* d_out, int out_size)
{
    const float* x  = (const float*)d_in[0];
    const float* We = (const float*)d_in[1];
    const float* Ue = (const float*)d_in[2];
    const float* be = (const float*)d_in[3];
    const float* Wd = (const float*)d_in[4];
    const float* Ud = (const float*)d_in[5];
    const float* bd = (const float*)d_in[6];
    const float* Wo = (const float*)d_in[7];
    const float* bo = (const float*)d_in[8];
    float* out = (float*)d_out;

    const int T = in_sizes[0] / (BB * FF);

    prep_kernel<<<64, 256>>>(Ue, Ud);

    cudaFuncSetAttribute(lstm_mma_kernel,
                         cudaFuncAttributeMaxDynamicSharedMemorySize, SMEM_BYTES);
    lstm_mma_kernel<<<(BB + MB - 1) / MB, NT, SMEM_BYTES>>>(x, We, be, Wd, bd, Wo, bo, out, T);
}